// round 15
// baseline (speedup 1.0000x reference)
#include <cuda_runtime.h>

// ProtoLayer (Kendall rank correlation) — fused bit-pack + popcount.
// FFMA2 packed diffs (fma pipe) + SHF funnel packing (alu pipe).
// LDG.128-grouped proto bits; PDL overlap of proto_build with tau prologue.
//
// B=4, Q=75, P=5, D=640. n_pairs = 640*639/2 = 204480.
// Pair set (order-free): all unordered pairs at circular distance 1..320,
// distance-320 half deduped. Per-thread comparisons (element i, tbase=i&~31):
//   comparison m (0..31) of word j (j=0..10): xs[tbase + j*32 + m] > xs[i]
// diff d = fma(v, -1, xi) = xi - v (exact); sign(d)=1 iff v > xi (+0 ties -> 0).
// Packing: 4 funnel-shift chains + PRMT assembly (bit permutation identical
// for q and p, so popc(q^p) unchanged; edge masks built in permuted domain):
//   word 0 keeps dist>=1, word 10 keeps dist<=320 (dedup for i>=320).
//   sum_pairs sq*sp = NPAIRS - 2*popc(Gq ^ Gp)

#define DIM     640
#define BB      4
#define QQ      75
#define PP      5
#define NQ      (BB * QQ)     // 300
#define NP      (BB * PP)     // 20
#define NJ      11            // words per element
#define NPAIRS  204480

// Proto bit layout per batch b (word pairs jp=0..4 cover words 0..9):
//   g_A[b][jp][i] = {p0.w(2jp), p0.w(2jp+1), p1.w(2jp), p1.w(2jp+1)}
//   g_B[b][jp][i] = same for protos 2,3
//   g_C[b][jp][i] = {p4.w(2jp), p4.w(2jp+1)}
//   g_S[b][i]     = {p0.w10, p1.w10, p2.w10, p3.w10};  g_S4[b][i] = p4.w10
__device__ __align__(16) uint4 g_A[BB][5][DIM];
__device__ __align__(16) uint4 g_B[BB][5][DIM];
__device__ __align__(16) uint2 g_C[BB][5][DIM];
__device__ __align__(16) uint4 g_S[BB][DIM];
__device__ unsigned g_S4[BB][DIM];

// Permuted-domain mask: set bits for comparisons m <= s (s in [-1, 31]).
// Comparison m = 4c + k sits at assembled bit 8k + (7 - c).
__device__ __forceinline__ unsigned low_mask_perm(int s)
{
    unsigned msk = 0;
#pragma unroll
    for (int k = 0; k < 4; k++) {
        const int n = (s >= k) ? (((s - k) >> 2) + 1) : 0;   // #c with 4c+k <= s
        msk |= ((0xFFu << (8 - n)) & 0xFFu) << (8 * k);      // top-n bits of byte k
    }
    return msk;
}

__device__ __forceinline__ unsigned long long dup2(float x)
{
    unsigned long long r;
    asm("mov.b64 %0, {%1, %1};" : "=l"(r) : "f"(x));
    return r;
}

// Build one 32-comparison word. FFMA2 gives two diffs per fma-pipe issue.
__device__ __forceinline__ unsigned build_word(const float4* __restrict__ ch,
                                               unsigned long long xi2,
                                               unsigned long long neg1)
{
    unsigned b0 = 0, b1 = 0, b2 = 0, b3 = 0;
#pragma unroll
    for (int c = 0; c < 8; c++) {
        const float4 v = ch[c];                   // LDS.128 (warp-uniform addr)
        unsigned long long v01, v23, d01, d23;
        asm("mov.b64 %0, {%1, %2};" : "=l"(v01) : "f"(v.x), "f"(v.y));
        asm("mov.b64 %0, {%1, %2};" : "=l"(v23) : "f"(v.z), "f"(v.w));
        asm("fma.rn.f32x2 %0, %1, %2, %3;" : "=l"(d01) : "l"(v01), "l"(neg1), "l"(xi2));
        asm("fma.rn.f32x2 %0, %1, %2, %3;" : "=l"(d23) : "l"(v23), "l"(neg1), "l"(xi2));
        unsigned r0, r1, r2, r3;
        asm("mov.b64 {%0, %1}, %2;" : "=r"(r0), "=r"(r1) : "l"(d01));
        asm("mov.b64 {%0, %1}, %2;" : "=r"(r2), "=r"(r3) : "l"(d23));
        b0 = __funnelshift_l(r0, b0, 1);          // SHF: b = (b<<1)|(d>>31)
        b1 = __funnelshift_l(r1, b1, 1);
        b2 = __funnelshift_l(r2, b2, 1);
        b3 = __funnelshift_l(r3, b3, 1);
    }
    const unsigned r01 = __byte_perm(b0, b1, 0x0040);
    const unsigned r23 = __byte_perm(b2, b3, 0x0040);
    return __byte_perm(r01, r23, 0x5410);
}

// grid = (NP, 2) — block (vec, half): half 0 -> words 0..5, half 1 -> 6..10.
__global__ __launch_bounds__(DIM) void proto_build_kernel(const float* __restrict__ pf)
{
    __shared__ __align__(16) float xs[2 * DIM];
    const int vec = blockIdx.x;
    const int b   = vec / PP;
    const int p   = vec % PP;
    const int i   = threadIdx.x;

    const float xi = pf[(size_t)vec * DIM + i];
    xs[i]       = xi;
    xs[i + DIM] = xi;
    __syncthreads();

    const int r     = i & 31;
    const int tbase = i & ~31;
    const unsigned long long xi2  = dup2(xi);
    const unsigned long long neg1 = dup2(-1.0f);

    const int j0 = blockIdx.y ? 6 : 0;
    const int j1 = blockIdx.y ? 11 : 6;
    for (int j = j0; j < j1; j++) {
        unsigned w = build_word((const float4*)(xs + tbase + j * 32), xi2, neg1);
        if (j == 0)      w &= ~low_mask_perm(r);                          // dist >= 1
        if (j == NJ - 1) w &=  low_mask_perm((i < 320) ? r : r - 1);      // dist <= 320

        if (j < 10) {
            const int jp = j >> 1, s = j & 1;
            if      (p == 0) ((unsigned*)&g_A[b][jp][i])[s]     = w;
            else if (p == 1) ((unsigned*)&g_A[b][jp][i])[2 + s] = w;
            else if (p == 2) ((unsigned*)&g_B[b][jp][i])[s]     = w;
            else if (p == 3) ((unsigned*)&g_B[b][jp][i])[2 + s] = w;
            else             ((unsigned*)&g_C[b][jp][i])[s]     = w;
        } else {
            if (p < 4) ((unsigned*)&g_S[b][i])[p] = w;
            else       g_S4[b][i] = w;
        }
    }
}

// grid = NQ (one block per query), block = 640, natural regs (cap 51).
__global__ __launch_bounds__(DIM, 2) void tau_kernel(const float* __restrict__ qf,
                                                     float* __restrict__ out)
{
    __shared__ __align__(16) float xs[2 * DIM];
    __shared__ int s_part[PP][DIM / 32];       // 5 x 20 per-warp partials

    const int bq = blockIdx.x;                 // query index (b*QQ + q)
    const int b  = bq / QQ;
    const int i  = threadIdx.x;

    const float xi = qf[(size_t)bq * DIM + i];
    xs[i]       = xi;
    xs[i + DIM] = xi;
    __syncthreads();

    const int r     = i & 31;
    const int tbase = i & ~31;
    const unsigned long long xi2  = dup2(xi);
    const unsigned long long neg1 = dup2(-1.0f);
    const unsigned m0  = ~low_mask_perm(r);
    const unsigned m10 =  low_mask_perm((i < 320) ? r : r - 1);

    // PDL: everything above runs concurrently with proto_build_kernel's tail.
    // Wait for its completion (implicit trigger at its kernel end) before
    // touching g_* proto bits.
    cudaGridDependencySynchronize();

    int ds[PP] = {0, 0, 0, 0, 0};
#pragma unroll
    for (int jp = 0; jp < 5; jp++) {
        unsigned w0 = build_word((const float4*)(xs + tbase + (2 * jp) * 32), xi2, neg1);
        const uint4 a  = g_A[b][jp][i];        // LDG.128 — latency covered by
        const uint4 bb = g_B[b][jp][i];        // the ~60-op w1 build below
        const uint2 c  = g_C[b][jp][i];        // LDG.64
        unsigned w1 = build_word((const float4*)(xs + tbase + (2 * jp + 1) * 32), xi2, neg1);
        if (jp == 0) w0 &= m0;
        ds[0] += __popc(w0 ^ a.x)  + __popc(w1 ^ a.y);
        ds[1] += __popc(w0 ^ a.z)  + __popc(w1 ^ a.w);
        ds[2] += __popc(w0 ^ bb.x) + __popc(w1 ^ bb.y);
        ds[3] += __popc(w0 ^ bb.z) + __popc(w1 ^ bb.w);
        ds[4] += __popc(w0 ^ c.x)  + __popc(w1 ^ c.y);
    }
    {   // word 10 (single)
        const uint4 sv    = g_S[b][i];         // LDG.128
        const unsigned s4 = g_S4[b][i];        // LDG.32
        unsigned w = build_word((const float4*)(xs + tbase + 10 * 32), xi2, neg1);
        w &= m10;
        ds[0] += __popc(w ^ sv.x);
        ds[1] += __popc(w ^ sv.y);
        ds[2] += __popc(w ^ sv.z);
        ds[3] += __popc(w ^ sv.w);
        ds[4] += __popc(w ^ s4);
    }

    const int warp = i >> 5;
    const int lane = i & 31;
#pragma unroll
    for (int p = 0; p < PP; p++) {
        const int c = __reduce_add_sync(0xffffffffu, ds[p]);   // REDUX.SUM
        if (lane == 0) s_part[p][warp] = c;
    }
    __syncthreads();

    if (warp < PP) {                            // warp w reduces proto p = w
        const int v = (lane < DIM / 32) ? s_part[warp][lane] : 0;
        const int s = __reduce_add_sync(0xffffffffu, v);
        if (lane == 0)
            out[bq * PP + warp] = (float)(NPAIRS - 2 * s) / (float)NPAIRS;
    }
}

extern "C" void kernel_launch(void* const* d_in, const int* in_sizes, int n_in,
                              void* d_out, int out_size)
{
    const float* qf = (const float*)d_in[0];   // query_feat (4,75,640)
    const float* pf = (const float*)d_in[1];   // proto_feat (4,5,640)
    if (n_in >= 2 && in_sizes[0] < in_sizes[1]) {   // defensive: query is larger
        const float* t = qf; qf = pf; pf = t;
    }

    proto_build_kernel<<<dim3(NP, 2), DIM>>>(pf);

    // tau with Programmatic Dependent Launch: may start while proto_build is
    // still running; tau blocks wait via cudaGridDependencySynchronize().
    cudaLaunchConfig_t cfg = {};
    cfg.gridDim  = dim3(NQ);
    cfg.blockDim = dim3(DIM);
    cudaLaunchAttribute attr[1];
    attr[0].id = cudaLaunchAttributeProgrammaticStreamSerialization;
    attr[0].val.programmaticStreamSerializationAllowed = 1;
    cfg.attrs    = attr;
    cfg.numAttrs = 1;
    float* outp = (float*)d_out;
    cudaLaunchKernelEx(&cfg, tau_kernel, qf, outp);
}

// round 17
// speedup vs baseline: 1.0190x; 1.0190x over previous
#include <cuda_runtime.h>

// ProtoLayer (Kendall rank correlation) — fused bit-pack + popcount.
// FFMA2 packed diffs (fma pipe) + SHF funnel packing (alu pipe).
// Proto bits regrouped for LDG.128 + L1 prefetch pipeline (R12 config,
// best timed: 14.8us) with amortized (NP,2) proto build.
// [Resubmission of R16 — previous round failed on infra, no data produced.]
//
// B=4, Q=75, P=5, D=640. n_pairs = 640*639/2 = 204480.
// Pair set (order-free): all unordered pairs at circular distance 1..320,
// distance-320 half deduped. Per-thread comparisons (element i, tbase=i&~31):
//   comparison m (0..31) of word j (j=0..10): xs[tbase + j*32 + m] > xs[i]
// diff d = fma(v, -1, xi) = xi - v (exact); sign(d)=1 iff v > xi (+0 ties -> 0).
// Packing: 4 funnel-shift chains + PRMT assembly (bit permutation identical
// for q and p, so popc(q^p) unchanged; edge masks built in permuted domain):
//   word 0 keeps dist>=1, word 10 keeps dist<=320 (dedup for i>=320).
//   sum_pairs sq*sp = NPAIRS - 2*popc(Gq ^ Gp)

#define DIM     640
#define BB      4
#define QQ      75
#define PP      5
#define NQ      (BB * QQ)     // 300
#define NP      (BB * PP)     // 20
#define NJ      11            // words per element
#define NPAIRS  204480

// Proto bit layout per batch b (word pairs jp=0..4 cover words 0..9):
//   g_A[b][jp][i] = {p0.w(2jp), p0.w(2jp+1), p1.w(2jp), p1.w(2jp+1)}
//   g_B[b][jp][i] = same for protos 2,3
//   g_C[b][jp][i] = {p4.w(2jp), p4.w(2jp+1)}
//   g_S[b][i]     = {p0.w10, p1.w10, p2.w10, p3.w10};  g_S4[b][i] = p4.w10
__device__ __align__(16) uint4 g_A[BB][5][DIM];
__device__ __align__(16) uint4 g_B[BB][5][DIM];
__device__ __align__(16) uint2 g_C[BB][5][DIM];
__device__ __align__(16) uint4 g_S[BB][DIM];
__device__ unsigned g_S4[BB][DIM];

__device__ __forceinline__ void prefetch_l1(const void* p)
{
    asm volatile("prefetch.global.L1 [%0];" :: "l"(p));
}

// Permuted-domain mask: set bits for comparisons m <= s (s in [-1, 31]).
// Comparison m = 4c + k sits at assembled bit 8k + (7 - c).
__device__ __forceinline__ unsigned low_mask_perm(int s)
{
    unsigned msk = 0;
#pragma unroll
    for (int k = 0; k < 4; k++) {
        const int n = (s >= k) ? (((s - k) >> 2) + 1) : 0;   // #c with 4c+k <= s
        msk |= ((0xFFu << (8 - n)) & 0xFFu) << (8 * k);      // top-n bits of byte k
    }
    return msk;
}

__device__ __forceinline__ unsigned long long dup2(float x)
{
    unsigned long long r;
    asm("mov.b64 %0, {%1, %1};" : "=l"(r) : "f"(x));
    return r;
}

// Build one 32-comparison word. FFMA2 gives two diffs per fma-pipe issue.
__device__ __forceinline__ unsigned build_word(const float4* __restrict__ ch,
                                               unsigned long long xi2,
                                               unsigned long long neg1)
{
    unsigned b0 = 0, b1 = 0, b2 = 0, b3 = 0;
#pragma unroll
    for (int c = 0; c < 8; c++) {
        const float4 v = ch[c];                   // LDS.128 (warp-uniform addr)
        unsigned long long v01, v23, d01, d23;
        asm("mov.b64 %0, {%1, %2};" : "=l"(v01) : "f"(v.x), "f"(v.y));
        asm("mov.b64 %0, {%1, %2};" : "=l"(v23) : "f"(v.z), "f"(v.w));
        asm("fma.rn.f32x2 %0, %1, %2, %3;" : "=l"(d01) : "l"(v01), "l"(neg1), "l"(xi2));
        asm("fma.rn.f32x2 %0, %1, %2, %3;" : "=l"(d23) : "l"(v23), "l"(neg1), "l"(xi2));
        unsigned r0, r1, r2, r3;
        asm("mov.b64 {%0, %1}, %2;" : "=r"(r0), "=r"(r1) : "l"(d01));
        asm("mov.b64 {%0, %1}, %2;" : "=r"(r2), "=r"(r3) : "l"(d23));
        b0 = __funnelshift_l(r0, b0, 1);          // SHF: b = (b<<1)|(d>>31)
        b1 = __funnelshift_l(r1, b1, 1);
        b2 = __funnelshift_l(r2, b2, 1);
        b3 = __funnelshift_l(r3, b3, 1);
    }
    const unsigned r01 = __byte_perm(b0, b1, 0x0040);
    const unsigned r23 = __byte_perm(b2, b3, 0x0040);
    return __byte_perm(r01, r23, 0x5410);
}

// grid = (NP, 2) — block (vec, half): half 0 -> words 0..5, half 1 -> 6..10.
__global__ __launch_bounds__(DIM) void proto_build_kernel(const float* __restrict__ pf)
{
    __shared__ __align__(16) float xs[2 * DIM];
    const int vec = blockIdx.x;
    const int b   = vec / PP;
    const int p   = vec % PP;
    const int i   = threadIdx.x;

    const float xi = pf[(size_t)vec * DIM + i];
    xs[i]       = xi;
    xs[i + DIM] = xi;
    __syncthreads();

    const int r     = i & 31;
    const int tbase = i & ~31;
    const unsigned long long xi2  = dup2(xi);
    const unsigned long long neg1 = dup2(-1.0f);

    const int j0 = blockIdx.y ? 6 : 0;
    const int j1 = blockIdx.y ? 11 : 6;
    for (int j = j0; j < j1; j++) {
        unsigned w = build_word((const float4*)(xs + tbase + j * 32), xi2, neg1);
        if (j == 0)      w &= ~low_mask_perm(r);                          // dist >= 1
        if (j == NJ - 1) w &=  low_mask_perm((i < 320) ? r : r - 1);      // dist <= 320

        if (j < 10) {
            const int jp = j >> 1, s = j & 1;
            if      (p == 0) ((unsigned*)&g_A[b][jp][i])[s]     = w;
            else if (p == 1) ((unsigned*)&g_A[b][jp][i])[2 + s] = w;
            else if (p == 2) ((unsigned*)&g_B[b][jp][i])[s]     = w;
            else if (p == 3) ((unsigned*)&g_B[b][jp][i])[2 + s] = w;
            else             ((unsigned*)&g_C[b][jp][i])[s]     = w;
        } else {
            if (p < 4) ((unsigned*)&g_S[b][i])[p] = w;
            else       g_S4[b][i] = w;
        }
    }
}

// grid = NQ (one block per query), block = 640. (R12 config — timed best.)
__global__ __launch_bounds__(DIM, 2) void tau_kernel(const float* __restrict__ qf,
                                                     float* __restrict__ out)
{
    __shared__ __align__(16) float xs[2 * DIM];
    __shared__ int s_part[PP][DIM / 32];       // 5 x 20 per-warp partials

    const int bq = blockIdx.x;                 // query index (b*QQ + q)
    const int b  = bq / QQ;
    const int i  = threadIdx.x;

    // warm L1 with the first jp's proto lines before doing smem prologue
    prefetch_l1(&g_A[b][0][i]);
    prefetch_l1(&g_B[b][0][i]);
    prefetch_l1(&g_C[b][0][i]);

    const float xi = qf[(size_t)bq * DIM + i];
    xs[i]       = xi;
    xs[i + DIM] = xi;
    __syncthreads();

    const int r     = i & 31;
    const int tbase = i & ~31;
    const unsigned long long xi2  = dup2(xi);
    const unsigned long long neg1 = dup2(-1.0f);
    const unsigned m0  = ~low_mask_perm(r);
    const unsigned m10 =  low_mask_perm((i < 320) ? r : r - 1);

    int ds[PP] = {0, 0, 0, 0, 0};
#pragma unroll
    for (int jp = 0; jp < 5; jp++) {
        if (jp < 4) {                          // prefetch next iteration's lines
            prefetch_l1(&g_A[b][jp + 1][i]);
            prefetch_l1(&g_B[b][jp + 1][i]);
            prefetch_l1(&g_C[b][jp + 1][i]);
        } else {
            prefetch_l1(&g_S[b][i]);
            prefetch_l1(&g_S4[b][i]);
        }
        unsigned w0 = build_word((const float4*)(xs + tbase + (2 * jp) * 32), xi2, neg1);
        unsigned w1 = build_word((const float4*)(xs + tbase + (2 * jp + 1) * 32), xi2, neg1);
        if (jp == 0) w0 &= m0;

        const uint4 a  = g_A[b][jp][i];        // LDG.128
        const uint4 bb = g_B[b][jp][i];        // LDG.128
        const uint2 c  = g_C[b][jp][i];        // LDG.64
        ds[0] += __popc(w0 ^ a.x)  + __popc(w1 ^ a.y);
        ds[1] += __popc(w0 ^ a.z)  + __popc(w1 ^ a.w);
        ds[2] += __popc(w0 ^ bb.x) + __popc(w1 ^ bb.y);
        ds[3] += __popc(w0 ^ bb.z) + __popc(w1 ^ bb.w);
        ds[4] += __popc(w0 ^ c.x)  + __popc(w1 ^ c.y);
    }
    {   // word 10 (single)
        unsigned w = build_word((const float4*)(xs + tbase + 10 * 32), xi2, neg1);
        w &= m10;
        const uint4 s = g_S[b][i];             // LDG.128
        ds[0] += __popc(w ^ s.x);
        ds[1] += __popc(w ^ s.y);
        ds[2] += __popc(w ^ s.z);
        ds[3] += __popc(w ^ s.w);
        ds[4] += __popc(w ^ g_S4[b][i]);       // LDG.32
    }

    const int warp = i >> 5;
    const int lane = i & 31;
#pragma unroll
    for (int p = 0; p < PP; p++) {
        const int c = __reduce_add_sync(0xffffffffu, ds[p]);   // REDUX.SUM
        if (lane == 0) s_part[p][warp] = c;
    }
    __syncthreads();

    if (warp < PP) {                            // warp w reduces proto p = w
        const int v = (lane < DIM / 32) ? s_part[warp][lane] : 0;
        const int s = __reduce_add_sync(0xffffffffu, v);
        if (lane == 0)
            out[bq * PP + warp] = (float)(NPAIRS - 2 * s) / (float)NPAIRS;
    }
}

extern "C" void kernel_launch(void* const* d_in, const int* in_sizes, int n_in,
                              void* d_out, int out_size)
{
    const float* qf = (const float*)d_in[0];   // query_feat (4,75,640)
    const float* pf = (const float*)d_in[1];   // proto_feat (4,5,640)
    if (n_in >= 2 && in_sizes[0] < in_sizes[1]) {   // defensive: query is larger
        const float* t = qf; qf = pf; pf = t;
    }

    proto_build_kernel<<<dim3(NP, 2), DIM>>>(pf);
    tau_kernel<<<NQ, DIM>>>(qf, (float*)d_out);
}